// round 6
// baseline (speedup 1.0000x reference)
#include <cuda_runtime.h>
#include <math.h>

#define RES      2048
#define STEPS    65536
#define W        32
#define CHUNK    128
#define TILE     64
#define EPAD     72
#define NTHREADS 256
#define BATCH    16
#define NB       (CHUNK / BATCH)
#define AA       5000.0f            // 1/(2 sigma^2)
#define DLT      (1.0f/2048.0f)
#define AD2      0.0011920929f      // AA * DLT^2
#define INV2SIG2 5000.0f

__device__ __forceinline__ unsigned to_tf32(float f) {
    unsigned r; asm("cvt.rna.tf32.f32 %0, %1;" : "=r"(r) : "f"(f)); return r;
}

__device__ __forceinline__ void red_add_v2(float* p, float a, float b) {
    asm volatile("red.global.add.v2.f32 [%0], {%1, %2};"
                 :: "l"(p), "f"(a), "f"(b) : "memory");
}

__global__ __launch_bounds__(NTHREADS, 4)
void bezier_raster_kernel(const float* __restrict__ cp, float* __restrict__ out)
{
    __shared__ float sCx[CHUNK], sCy[CHUNK];
    __shared__ int   sBx[CHUNK], sBy[CHUNK];
    __shared__ float sW[2][CHUNK], sE[2][CHUNK];
    __shared__ int   sMinX, sMaxX, sMinY, sMaxY;
    __shared__ int   sBminX[NB], sBmaxX[NB], sBminY[NB], sBmaxY[NB];
    __shared__ unsigned ebx[2][BATCH][EPAD];        // A: [k][row], tf32 bits
    __shared__ unsigned eby[2][BATCH][8][8];        // B: [k][col%8][col/8], tf32 bits

    const int tid = threadIdx.x;
    const int s0  = blockIdx.x * CHUNK;

    if (tid == 0) {
        sMinX = 0x7fffffff; sMaxX = -0x7fffffff;
        sMinY = 0x7fffffff; sMaxY = -0x7fffffff;
    }
    __syncthreads();

    // ---- Phase A: per-step curve point + block corner (fp64, 128 threads)
    if (tid < CHUNK) {
        const int s = s0 + tid;
        const double tl = (double)s * (1.0 / 65535.0);   // linspace(0,1,STEPS)
        const double to = (double)s * (1.0 / 65536.0);   // arange(STEPS)/STEPS
        const double p0x = (double)cp[0], p0y = (double)cp[1];
        const double p1x = (double)cp[2], p1y = (double)cp[3];
        const double p2x = (double)cp[4], p2y = (double)cp[5];
        const double ax = p0x + (p1x - p0x) * tl;
        const double bx = p1x + (p2x - p1x) * tl;
        const double ay = p0y + (p1y - p0y) * tl;
        const double by = p1y + (p2y - p1y) * tl;
        const double cx = ax + to * (bx - ax);
        const double cy = ay + to * (by - ay);
        int bxi = (int)floor((double)RES * cx) - W / 2;
        int byi = (int)floor((double)RES * cy) - W / 2;
        bxi = min(max(bxi, 0), RES - W);
        byi = min(max(byi, 0), RES - W);
        sCx[tid] = (float)cx; sCy[tid] = (float)cy;
        sBx[tid] = bxi;       sBy[tid] = byi;
        atomicMin(&sMinX, bxi); atomicMax(&sMaxX, bxi);
        atomicMin(&sMinY, byi); atomicMax(&sMaxY, byi);
    }
    __syncthreads();

    const int basex = sMinX;
    const int basey = sMinY & ~1;          // even -> 8B-aligned v2 reductions
    const float scale = 1.0f / (float)STEPS;   // 2^-16, exact

    // ---- Seeds: one thread per (step, axis); scale folded into x-seeds
    {
        const int st = tid >> 1;
        const int ax = tid & 1;
        const float c  = ax ? sCy[st] : sCx[st];
        const int   pb = ax ? basey   : basex;
        const float d00 = c - (float)pb * DLT;
        sW[ax][st] = __expf(-AA * d00 * d00) * (ax ? 1.0f : scale);
        sE[ax][st] = __expf(2.0f * AA * DLT * d00);
    }
    if (tid < 2 * NB) {
        const int b   = tid & (NB - 1);
        const int axs = tid >> 3;
        const int* src = axs ? sBy : sBx;
        int mn = 0x7fffffff, mx = -0x7fffffff;
        #pragma unroll
        for (int k = 0; k < BATCH; ++k) {
            const int v = src[b * BATCH + k];
            mn = min(mn, v); mx = max(mx, v);
        }
        if (axs) { sBminY[b] = mn; sBmaxY[b] = mx; }
        else     { sBminX[b] = mn; sBmaxX[b] = mx; }
    }
    __syncthreads();

    const bool ok = (sMaxX + W - basex <= TILE) && (sMaxY + W - basey <= TILE);

    if (ok) {
        // weight-gen decomposition: 16 steps x 2 axes x 8 sub-ranges
        const int gsloc = tid >> 4;
        const int gaxis = (tid >> 3) & 1;
        const int gsub  = tid & 7;
        const float CW  = __expf(-64.0f * AD2 * (float)(gsub * gsub));
        const float Crs = __expf(-16.0f * AD2 * (float)gsub);
        const float Gc  = __expf(-AD2);
        const float gc  = __expf(-2.0f * AD2);
        const int   gpb  = gaxis ? basey : basex;
        const int*  gblk = gaxis ? sBy : sBx;

        auto gen = [&](int b, int buf) {
            const int st  = b * BATCH + gsloc;
            const int blk = gblk[st];
            const float w00 = sW[gaxis][st];
            const float E   = sE[gaxis][st];
            const float E2 = E * E, E4 = E2 * E2, E8 = E4 * E4;
            float Ep = (gsub & 1) ? E8 : 1.0f;
            const float E16 = E8 * E8;   if (gsub & 2) Ep *= E16;
            const float E32 = E16 * E16; if (gsub & 4) Ep *= E32;
            float w = w00 * Ep * CW;
            float r = E * Gc * Crs;
            const int rel = gpb + gsub * 8 - blk;
            unsigned v[8];
            #pragma unroll
            for (int j = 0; j < 8; ++j) {
                const float wj = ((unsigned)(rel + j) < W) ? w : 0.0f;
                v[j] = to_tf32(wj);
                w *= r; r *= gc;
            }
            if (gaxis == 0) {
                *(uint4*)&ebx[buf][gsloc][gsub * 8]     = make_uint4(v[0], v[1], v[2], v[3]);
                *(uint4*)&ebx[buf][gsloc][gsub * 8 + 4] = make_uint4(v[4], v[5], v[6], v[7]);
            } else {
                #pragma unroll
                for (int j = 0; j < 8; ++j)
                    eby[buf][gsloc][j][gsub] = v[j];   // [k][col%8][col/8]
            }
        };

        const int lane = tid & 31;
        const int wid  = tid >> 5;
        const int g    = lane >> 2;
        const int t    = lane & 3;
        const int rb   = (wid >> 1) * 16;
        const int cb   = (wid & 1)  * 32;
        const int cb8  = cb >> 3;

        float c[4][4];
        #pragma unroll
        for (int n = 0; n < 4; ++n)
            #pragma unroll
            for (int i = 0; i < 4; ++i) c[n][i] = 0.0f;

        gen(0, 0);
        __syncthreads();

        for (int b = 0; b < NB; ++b) {
            const int cur = b & 1;
            if (b + 1 < NB) gen(b + 1, cur ^ 1);

            const int rlo = sBminX[b] - basex, rhi = sBmaxX[b] - basex + W;
            const int clo = sBminY[b] - basey, chi = sBmaxY[b] - basey + W;
            if ((rb + 16 > rlo) && (rb < rhi) && (cb + 32 > clo) && (cb < chi)) {
                #pragma unroll
                for (int ks = 0; ks < 2; ++ks) {
                    const int k0 = ks * 8;
                    const unsigned a0 = ebx[cur][k0 + t][rb + g];
                    const unsigned a1 = ebx[cur][k0 + t][rb + g + 8];
                    const unsigned a2 = ebx[cur][k0 + t + 4][rb + g];
                    const unsigned a3 = ebx[cur][k0 + t + 4][rb + g + 8];
                    const uint4 b0 = *(const uint4*)&eby[cur][k0 + t][g][cb8];
                    const uint4 b1 = *(const uint4*)&eby[cur][k0 + t + 4][g][cb8];
                    asm volatile(
                        "mma.sync.aligned.m16n8k8.row.col.f32.tf32.tf32.f32 "
                        "{%0,%1,%2,%3},{%4,%5,%6,%7},{%8,%9},{%0,%1,%2,%3};"
                        : "+f"(c[0][0]), "+f"(c[0][1]), "+f"(c[0][2]), "+f"(c[0][3])
                        : "r"(a0), "r"(a1), "r"(a2), "r"(a3), "r"(b0.x), "r"(b1.x));
                    asm volatile(
                        "mma.sync.aligned.m16n8k8.row.col.f32.tf32.tf32.f32 "
                        "{%0,%1,%2,%3},{%4,%5,%6,%7},{%8,%9},{%0,%1,%2,%3};"
                        : "+f"(c[1][0]), "+f"(c[1][1]), "+f"(c[1][2]), "+f"(c[1][3])
                        : "r"(a0), "r"(a1), "r"(a2), "r"(a3), "r"(b0.y), "r"(b1.y));
                    asm volatile(
                        "mma.sync.aligned.m16n8k8.row.col.f32.tf32.tf32.f32 "
                        "{%0,%1,%2,%3},{%4,%5,%6,%7},{%8,%9},{%0,%1,%2,%3};"
                        : "+f"(c[2][0]), "+f"(c[2][1]), "+f"(c[2][2]), "+f"(c[2][3])
                        : "r"(a0), "r"(a1), "r"(a2), "r"(a3), "r"(b0.z), "r"(b1.z));
                    asm volatile(
                        "mma.sync.aligned.m16n8k8.row.col.f32.tf32.tf32.f32 "
                        "{%0,%1,%2,%3},{%4,%5,%6,%7},{%8,%9},{%0,%1,%2,%3};"
                        : "+f"(c[3][0]), "+f"(c[3][1]), "+f"(c[3][2]), "+f"(c[3][3])
                        : "r"(a0), "r"(a1), "r"(a2), "r"(a3), "r"(b0.w), "r"(b1.w));
                }
            }
            __syncthreads();
        }

        // ---- Epilogue: paired v2 reductions (scale already folded in)
        const int row0 = basex + rb + g;
        const int row1 = row0 + 8;
        #pragma unroll
        for (int n = 0; n < 4; ++n) {
            const int col = basey + cb + n * 8 + 2 * t;
            if (row0 < RES && col < RES &&
                (__float_as_uint(c[n][0]) | __float_as_uint(c[n][1])))
                red_add_v2(&out[row0 * RES + col], c[n][0], c[n][1]);
            if (row1 < RES && col < RES &&
                (__float_as_uint(c[n][2]) | __float_as_uint(c[n][3])))
                red_add_v2(&out[row1 * RES + col], c[n][2], c[n][3]);
        }
    } else {
        // ---- Fallback (should never trigger for control points in [0,1])
        for (int sl = 0; sl < CHUNK; ++sl) {
            const int   blkx = sBx[sl], blky = sBy[sl];
            const float cx = sCx[sl], cy = sCy[sl];
            for (int c2 = tid; c2 < W * W; c2 += NTHREADS) {
                const int wi = c2 >> 5, wj = c2 & 31;
                const int gx = blkx + wi, gy = blky + wj;
                const float dx = cx - (float)gx * DLT;
                const float dy = cy - (float)gy * DLT;
                const float w = __expf(-INV2SIG2 * (dx * dx + dy * dy));
                atomicAdd(&out[gx * RES + gy], w * scale);
            }
        }
    }
}

extern "C" void kernel_launch(void* const* d_in, const int* in_sizes, int n_in,
                              void* d_out, int out_size)
{
    (void)in_sizes; (void)n_in;
    const float* cp = (const float*)d_in[0];
    float* out = (float*)d_out;
    cudaMemsetAsync(out, 0, (size_t)out_size * sizeof(float), 0);
    bezier_raster_kernel<<<STEPS / CHUNK, NTHREADS>>>(cp, out);
}

// round 8
// speedup vs baseline: 1.7044x; 1.7044x over previous
#include <cuda_runtime.h>
#include <cuda_fp16.h>
#include <math.h>

#define RES      2048
#define STEPS    65536
#define W        32
#define CHUNK    128
#define TILE     64
#define EPADH    72                 // halves per k-row (36 words: 4k mod 32 -> CF ldmatrix)
#define NTHREADS 256
#define BATCH    16
#define NB       (CHUNK / BATCH)
#define AA       5000.0f            // 1/(2 sigma^2)
#define DLT      (1.0f/2048.0f)
#define AD2      0.0011920929f      // AA * DLT^2
#define INV2SIG2 5000.0f
#define AXSCALE  0.00390625f        // 2^-8 per axis; product = 1/STEPS exactly

__global__ __launch_bounds__(NTHREADS, 4)
void bezier_raster_kernel(const float* __restrict__ cp, float* __restrict__ out)
{
    __shared__ float sCx[CHUNK], sCy[CHUNK];
    __shared__ int   sBx[CHUNK], sBy[CHUNK];
    __shared__ float sW[2][CHUNK], sE[2][CHUNK];
    __shared__ int   sMinX, sMaxX, sMinY, sMaxY;
    __shared__ int   sBminX[NB], sBmaxX[NB], sBminY[NB], sBmaxY[NB];
    __shared__ __align__(16) __half ebx[2][BATCH][EPADH];   // x-weights: [k][row]
    __shared__ __align__(16) __half eby[2][BATCH][EPADH];   // y-weights: [k][col]

    const int tid = threadIdx.x;
    const int s0  = blockIdx.x * CHUNK;

    if (tid == 0) {
        sMinX = 0x7fffffff; sMaxX = -0x7fffffff;
        sMinY = 0x7fffffff; sMaxY = -0x7fffffff;
    }
    __syncthreads();

    // ---- Phase A: per-step curve point + block corner (fp64, 128 threads)
    if (tid < CHUNK) {
        const int s = s0 + tid;
        const double tl = (double)s * (1.0 / 65535.0);   // linspace(0,1,STEPS)
        const double to = (double)s * (1.0 / 65536.0);   // arange(STEPS)/STEPS
        const double p0x = (double)cp[0], p0y = (double)cp[1];
        const double p1x = (double)cp[2], p1y = (double)cp[3];
        const double p2x = (double)cp[4], p2y = (double)cp[5];
        const double ax = p0x + (p1x - p0x) * tl;
        const double bx = p1x + (p2x - p1x) * tl;
        const double ay = p0y + (p1y - p0y) * tl;
        const double by = p1y + (p2y - p1y) * tl;
        const double cx = ax + to * (bx - ax);
        const double cy = ay + to * (by - ay);
        int bxi = (int)floor((double)RES * cx) - W / 2;
        int byi = (int)floor((double)RES * cy) - W / 2;
        bxi = min(max(bxi, 0), RES - W);
        byi = min(max(byi, 0), RES - W);
        sCx[tid] = (float)cx; sCy[tid] = (float)cy;
        sBx[tid] = bxi;       sBy[tid] = byi;
        atomicMin(&sMinX, bxi); atomicMax(&sMaxX, bxi);
        atomicMin(&sMinY, byi); atomicMax(&sMaxY, byi);
    }
    __syncthreads();

    const int basex = sMinX;
    const int basey = sMinY;

    // ---- Seeds: one thread per (step, axis); 2^-8 scale folded into EACH axis
    {
        const int st = tid >> 1;
        const int ax = tid & 1;
        const float c  = ax ? sCy[st] : sCx[st];
        const int   pb = ax ? basey   : basex;
        const float d00 = c - (float)pb * DLT;
        sW[ax][st] = __expf(-AA * d00 * d00) * AXSCALE;
        sE[ax][st] = __expf(2.0f * AA * DLT * d00);
    }
    if (tid < 2 * NB) {
        const int b   = tid & (NB - 1);
        const int axs = tid >> 3;
        const int* src = axs ? sBy : sBx;
        int mn = 0x7fffffff, mx = -0x7fffffff;
        #pragma unroll
        for (int k = 0; k < BATCH; ++k) {
            const int v = src[b * BATCH + k];
            mn = min(mn, v); mx = max(mx, v);
        }
        if (axs) { sBminY[b] = mn; sBmaxY[b] = mx; }
        else     { sBminX[b] = mn; sBmaxX[b] = mx; }
    }
    __syncthreads();

    const bool ok = (sMaxX + W - basex <= TILE) && (sMaxY + W - basey <= TILE);

    if (ok) {
        // weight-gen decomposition: 16 steps x 2 axes x 8 sub-ranges
        const int gsloc = tid >> 4;
        const int gaxis = (tid >> 3) & 1;
        const int gsub  = tid & 7;
        const float CW  = __expf(-64.0f * AD2 * (float)(gsub * gsub));
        const float Crs = __expf(-16.0f * AD2 * (float)gsub);
        const float Gc  = __expf(-AD2);
        const float gc  = __expf(-2.0f * AD2);
        const int   gpb  = gaxis ? basey : basex;
        const int*  gblk = gaxis ? sBy : sBx;

        auto gen = [&](int b, int buf) {
            const int st  = b * BATCH + gsloc;
            const int blk = gblk[st];
            const float w00 = sW[gaxis][st];
            const float E   = sE[gaxis][st];
            const float E2 = E * E, E4 = E2 * E2, E8 = E4 * E4;
            float Ep = (gsub & 1) ? E8 : 1.0f;
            const float E16 = E8 * E8;   if (gsub & 2) Ep *= E16;
            const float E32 = E16 * E16; if (gsub & 4) Ep *= E32;
            float w = w00 * Ep * CW;
            float r = E * Gc * Crs;
            const int rel = gpb + gsub * 8 - blk;
            float v[8];
            #pragma unroll
            for (int j = 0; j < 8; ++j) {
                v[j] = ((unsigned)(rel + j) < W) ? w : 0.0f;
                w *= r; r *= gc;
            }
            const __half2 h0 = __floats2half2_rn(v[0], v[1]);
            const __half2 h1 = __floats2half2_rn(v[2], v[3]);
            const __half2 h2 = __floats2half2_rn(v[4], v[5]);
            const __half2 h3 = __floats2half2_rn(v[6], v[7]);
            __half2* dst = (__half2*)(gaxis ? &eby[buf][gsloc][gsub * 8]
                                            : &ebx[buf][gsloc][gsub * 8]);
            *(uint4*)dst = make_uint4(*(const unsigned*)&h0, *(const unsigned*)&h1,
                                      *(const unsigned*)&h2, *(const unsigned*)&h3);
        };

        const int lane = tid & 31;
        const int wid  = tid >> 5;
        const int g    = lane >> 2;
        const int t    = lane & 3;
        const int rb   = (wid >> 1) * 16;
        const int cb   = (wid & 1)  * 32;

        // ldmatrix lane->address precompute (two buffers)
        const int kA   = (lane & 7) | ((lane & 16) >> 1);
        const int colA = rb + (lane & 8);
        const int kB   = lane & 15;
        const int colB = cb + ((lane & 16) >> 1);
        unsigned aAddr[2], bAddr0[2], bAddr1[2];
        #pragma unroll
        for (int bf = 0; bf < 2; ++bf) {
            aAddr[bf]  = (unsigned)__cvta_generic_to_shared(&ebx[bf][kA][colA]);
            bAddr0[bf] = (unsigned)__cvta_generic_to_shared(&eby[bf][kB][colB]);
            bAddr1[bf] = bAddr0[bf] + 32;   // +16 cols * 2B
        }

        float c[4][4];
        #pragma unroll
        for (int n = 0; n < 4; ++n)
            #pragma unroll
            for (int i = 0; i < 4; ++i) c[n][i] = 0.0f;

        gen(0, 0);
        __syncthreads();

        for (int b = 0; b < NB; ++b) {
            const int cur = b & 1;
            if (b + 1 < NB) gen(b + 1, cur ^ 1);

            const int rlo = sBminX[b] - basex, rhi = sBmaxX[b] - basex + W;
            const int clo = sBminY[b] - basey, chi = sBmaxY[b] - basey + W;
            if ((rb + 16 > rlo) && (rb < rhi) && (cb + 32 > clo) && (cb < chi)) {
                unsigned a0, a1, a2, a3, p0, p1, p2, p3, q0, q1, q2, q3;
                asm volatile("ldmatrix.sync.aligned.m8n8.x4.trans.shared.b16 {%0,%1,%2,%3}, [%4];"
                             : "=r"(a0), "=r"(a1), "=r"(a2), "=r"(a3) : "r"(aAddr[cur]));
                asm volatile("ldmatrix.sync.aligned.m8n8.x4.trans.shared.b16 {%0,%1,%2,%3}, [%4];"
                             : "=r"(p0), "=r"(p1), "=r"(p2), "=r"(p3) : "r"(bAddr0[cur]));
                asm volatile("ldmatrix.sync.aligned.m8n8.x4.trans.shared.b16 {%0,%1,%2,%3}, [%4];"
                             : "=r"(q0), "=r"(q1), "=r"(q2), "=r"(q3) : "r"(bAddr1[cur]));
                asm volatile("mma.sync.aligned.m16n8k16.row.col.f32.f16.f16.f32 "
                             "{%0,%1,%2,%3},{%4,%5,%6,%7},{%8,%9},{%0,%1,%2,%3};"
                             : "+f"(c[0][0]), "+f"(c[0][1]), "+f"(c[0][2]), "+f"(c[0][3])
                             : "r"(a0), "r"(a1), "r"(a2), "r"(a3), "r"(p0), "r"(p1));
                asm volatile("mma.sync.aligned.m16n8k16.row.col.f32.f16.f16.f32 "
                             "{%0,%1,%2,%3},{%4,%5,%6,%7},{%8,%9},{%0,%1,%2,%3};"
                             : "+f"(c[1][0]), "+f"(c[1][1]), "+f"(c[1][2]), "+f"(c[1][3])
                             : "r"(a0), "r"(a1), "r"(a2), "r"(a3), "r"(p2), "r"(p3));
                asm volatile("mma.sync.aligned.m16n8k16.row.col.f32.f16.f16.f32 "
                             "{%0,%1,%2,%3},{%4,%5,%6,%7},{%8,%9},{%0,%1,%2,%3};"
                             : "+f"(c[2][0]), "+f"(c[2][1]), "+f"(c[2][2]), "+f"(c[2][3])
                             : "r"(a0), "r"(a1), "r"(a2), "r"(a3), "r"(q0), "r"(q1));
                asm volatile("mma.sync.aligned.m16n8k16.row.col.f32.f16.f16.f32 "
                             "{%0,%1,%2,%3},{%4,%5,%6,%7},{%8,%9},{%0,%1,%2,%3};"
                             : "+f"(c[3][0]), "+f"(c[3][1]), "+f"(c[3][2]), "+f"(c[3][3])
                             : "r"(a0), "r"(a1), "r"(a2), "r"(a3), "r"(q2), "r"(q3));
            }
            __syncthreads();
        }

        // ---- Epilogue: scalar predicated reductions (scale pre-folded)
        const int row0 = basex + rb + g;
        const int row1 = row0 + 8;
        #pragma unroll
        for (int n = 0; n < 4; ++n) {
            const int col = basey + cb + n * 8 + 2 * t;
            if (c[n][0] != 0.0f && row0 < RES && col     < RES) atomicAdd(&out[row0 * RES + col],     c[n][0]);
            if (c[n][1] != 0.0f && row0 < RES && col + 1 < RES) atomicAdd(&out[row0 * RES + col + 1], c[n][1]);
            if (c[n][2] != 0.0f && row1 < RES && col     < RES) atomicAdd(&out[row1 * RES + col],     c[n][2]);
            if (c[n][3] != 0.0f && row1 < RES && col + 1 < RES) atomicAdd(&out[row1 * RES + col + 1], c[n][3]);
        }
    } else {
        // ---- Fallback (should never trigger for control points in [0,1])
        const float scale = 1.0f / (float)STEPS;
        for (int sl = 0; sl < CHUNK; ++sl) {
            const int   blkx = sBx[sl], blky = sBy[sl];
            const float cx = sCx[sl], cy = sCy[sl];
            for (int c2 = tid; c2 < W * W; c2 += NTHREADS) {
                const int wi = c2 >> 5, wj = c2 & 31;
                const int gx = blkx + wi, gy = blky + wj;
                const float dx = cx - (float)gx * DLT;
                const float dy = cy - (float)gy * DLT;
                const float w = __expf(-INV2SIG2 * (dx * dx + dy * dy));
                atomicAdd(&out[gx * RES + gy], w * scale);
            }
        }
    }
}

extern "C" void kernel_launch(void* const* d_in, const int* in_sizes, int n_in,
                              void* d_out, int out_size)
{
    (void)in_sizes; (void)n_in;
    const float* cp = (const float*)d_in[0];
    float* out = (float*)d_out;
    cudaMemsetAsync(out, 0, (size_t)out_size * sizeof(float), 0);
    bezier_raster_kernel<<<STEPS / CHUNK, NTHREADS>>>(cp, out);
}